// round 5
// baseline (speedup 1.0000x reference)
#include <cuda_runtime.h>
#include <math.h>

#define EPSF 1e-8f

// Scratch for FC output (512 x 134). __device__ global = allowed scratch.
__device__ float g_fc[512 * 134];

__device__ __forceinline__ float softplus_f(float x) {
    return (x > 20.0f) ? x : log1pf(expf(x));
}

// ---------------------------------------------------------------------------
// Kernel 1: out[b, j] = sum_c co[b, c] * W[c, j] + bias[j]
// Grid: 128 CTAs, 4 batch rows each. W streamed coalesced (j contiguous),
// co rows staged in SMEM (broadcast reads). FFMA-bound, ~5 us.
// ---------------------------------------------------------------------------
__global__ __launch_bounds__(256) void fc_kernel(const float* __restrict__ co,
                                                 const float* __restrict__ W,
                                                 const float* __restrict__ bias) {
    __shared__ __align__(16) float s_co[4 * 1024];
    const int b0 = blockIdx.x * 4;
    const int tid = threadIdx.x;

    const float4* co4 = (const float4*)(co + (size_t)b0 * 1024);
    float4* s4 = (float4*)s_co;
#pragma unroll
    for (int i = 0; i < 4; ++i)
        s4[tid + i * 256] = co4[tid + i * 256];
    __syncthreads();

    if (tid < 134) {
        float a0 = 0.f, a1 = 0.f, a2 = 0.f, a3 = 0.f;
#pragma unroll 4
        for (int c = 0; c < 1024; c += 4) {
            float w0 = W[(c + 0) * 134 + tid];
            float w1 = W[(c + 1) * 134 + tid];
            float w2 = W[(c + 2) * 134 + tid];
            float w3 = W[(c + 3) * 134 + tid];
            float4 x0 = *(const float4*)&s_co[0 * 1024 + c];
            float4 x1 = *(const float4*)&s_co[1 * 1024 + c];
            float4 x2 = *(const float4*)&s_co[2 * 1024 + c];
            float4 x3 = *(const float4*)&s_co[3 * 1024 + c];
            a0 += w0 * x0.x + w1 * x0.y + w2 * x0.z + w3 * x0.w;
            a1 += w0 * x1.x + w1 * x1.y + w2 * x1.z + w3 * x1.w;
            a2 += w0 * x2.x + w1 * x2.y + w2 * x2.z + w3 * x2.w;
            a3 += w0 * x3.x + w1 * x3.y + w2 * x3.z + w3 * x3.w;
        }
        float bj = bias[tid];
        g_fc[(b0 + 0) * 134 + tid] = a0 + bj;
        g_fc[(b0 + 1) * 134 + tid] = a1 + bj;
        g_fc[(b0 + 2) * 134 + tid] = a2 + bj;
        g_fc[(b0 + 3) * 134 + tid] = a3 + bj;
    }
}

// ---------------------------------------------------------------------------
// Block reduction helpers (512 threads = 16 warps).
// ---------------------------------------------------------------------------
__device__ __forceinline__ float block_sum(float v, float* s_red, int wid, int lane) {
#pragma unroll
    for (int o = 16; o; o >>= 1) v += __shfl_xor_sync(0xffffffffu, v, o);
    __syncthreads();                 // protect s_red reuse from prior call
    if (lane == 0) s_red[wid] = v;
    __syncthreads();
    if (wid == 0) {
        float x = (lane < 16) ? s_red[lane] : 0.0f;
#pragma unroll
        for (int o = 8; o; o >>= 1) x += __shfl_xor_sync(0xffffffffu, x, o);
        if (lane == 0) s_red[16] = x;
    }
    __syncthreads();
    return s_red[16];
}

__device__ __forceinline__ float block_max(float v, float* s_red, int wid, int lane) {
#pragma unroll
    for (int o = 16; o; o >>= 1) v = fmaxf(v, __shfl_xor_sync(0xffffffffu, v, o));
    __syncthreads();
    if (lane == 0) s_red[wid] = v;
    __syncthreads();
    if (wid == 0) {
        float x = (lane < 16) ? s_red[lane] : -3.4e38f;
#pragma unroll
        for (int o = 8; o; o >>= 1) x = fmaxf(x, __shfl_xor_sync(0xffffffffu, x, o));
        if (lane == 0) s_red[16] = x;
    }
    __syncthreads();
    return s_red[16];
}

// ---------------------------------------------------------------------------
// Kernel 2: fully fused NTM head. One CTA per batch row (grid 512, 512 thr).
//   Phase A: unpack fc_out -> k, beta, g, s, gamma; ||k||.
//   Phase B: sim[n] (cosine) via warp-parallel rows, float4 streaming.
//   Phase C: softmax over N, interpolate with prev_w, shift conv, sharpen.
//   Phase D: read_vec = w @ mem (re-read slab; expected L2-resident).
// ---------------------------------------------------------------------------
__global__ __launch_bounds__(512, 2) void ntm_kernel(const float* __restrict__ mem,
                                                     const float* __restrict__ prev_w,
                                                     float* __restrict__ d_out) {
    __shared__ __align__(16) float s_k[128];
    __shared__ float s_raw[6];
    __shared__ float s_scal[8];      // beta, g, s0, s1, s2, gamma, inv_norm_k
    __shared__ float s_logit[512];
    __shared__ float s_wg[512];
    __shared__ float s_w[512];
    __shared__ __align__(16) float s_part[16 * 128];
    __shared__ float s_red[17];

    const int b = blockIdx.x;
    const int tid = threadIdx.x;
    const int wid = tid >> 5;
    const int lane = tid & 31;

    // ---- Phase A: load fc row, compute scalar gates ----
    const float* fcb = g_fc + b * 134;
    if (tid < 128) s_k[tid] = fcb[tid];
    else if (tid < 134) s_raw[tid - 128] = fcb[tid];
    __syncthreads();

    if (tid == 0) {
        float beta = softplus_f(s_raw[0]);
        float g = 1.0f / (1.0f + expf(-s_raw[1]));
        float x0 = s_raw[2], x1 = s_raw[3], x2 = s_raw[4];
        float mx = fmaxf(x0, fmaxf(x1, x2));
        float e0 = expf(x0 - mx), e1 = expf(x1 - mx), e2 = expf(x2 - mx);
        float inv = 1.0f / (e0 + e1 + e2);
        float gamma = 1.0f + softplus_f(s_raw[5]);
        s_scal[0] = beta; s_scal[1] = g;
        s_scal[2] = e0 * inv; s_scal[3] = e1 * inv; s_scal[4] = e2 * inv;
        s_scal[5] = gamma;
    }
    if (wid == 0) {
        float4 k4 = ((const float4*)s_k)[lane];
        float ss = k4.x * k4.x + k4.y * k4.y + k4.z * k4.z + k4.w * k4.w;
#pragma unroll
        for (int o = 16; o; o >>= 1) ss += __shfl_xor_sync(0xffffffffu, ss, o);
        if (lane == 0) s_scal[6] = 1.0f / (sqrtf(ss) + EPSF);
    }
    __syncthreads();

    const float beta = s_scal[0];
    const float inv_nk = s_scal[6];
    const float4 k4 = ((const float4*)s_k)[lane];
    const float4* memb4 = (const float4*)(mem + (size_t)b * (512 * 128));

    // ---- Phase B: sim logits (warp wid owns rows [wid*32, wid*32+32)) ----
#pragma unroll 2
    for (int r = 0; r < 32; r += 2) {
        int n0 = wid * 32 + r;
        float4 v0 = memb4[n0 * 32 + lane];
        float4 v1 = memb4[(n0 + 1) * 32 + lane];
        float d0 = v0.x * k4.x + v0.y * k4.y + v0.z * k4.z + v0.w * k4.w;
        float q0 = v0.x * v0.x + v0.y * v0.y + v0.z * v0.z + v0.w * v0.w;
        float d1 = v1.x * k4.x + v1.y * k4.y + v1.z * k4.z + v1.w * k4.w;
        float q1 = v1.x * v1.x + v1.y * v1.y + v1.z * v1.z + v1.w * v1.w;
#pragma unroll
        for (int o = 16; o; o >>= 1) {
            d0 += __shfl_xor_sync(0xffffffffu, d0, o);
            q0 += __shfl_xor_sync(0xffffffffu, q0, o);
            d1 += __shfl_xor_sync(0xffffffffu, d1, o);
            q1 += __shfl_xor_sync(0xffffffffu, q1, o);
        }
        if (lane == 0) {
            s_logit[n0]     = beta * d0 * inv_nk / (sqrtf(q0) + EPSF);
            s_logit[n0 + 1] = beta * d1 * inv_nk / (sqrtf(q1) + EPSF);
        }
    }
    __syncthreads();

    // ---- Phase C: softmax over N, gate, shift, sharpen ----
    float logit = s_logit[tid];
    float vmax = block_max(logit, s_red, wid, lane);
    float e = expf(logit - vmax);
    float esum = block_sum(e, s_red, wid, lane);
    float w_c = e / esum;

    float g = s_scal[1];
    float wg = g * w_c + (1.0f - g) * prev_w[b * 512 + tid];
    s_wg[tid] = wg;
    __syncthreads();

    float ws = s_scal[2] * s_wg[(tid + 511) & 511]
             + s_scal[3] * wg
             + s_scal[4] * s_wg[(tid + 1) & 511];
    float wp = expf(s_scal[5] * logf(ws));   // ws > 0 always
    float psum = block_sum(wp, s_red, wid, lane);
    float w = wp / (psum + EPSF);
    s_w[tid] = w;
    d_out[512 * 128 + b * 512 + tid] = w;    // output w (second tuple element)
    __syncthreads();

    // ---- Phase D: read_vec[m] = sum_n w[n] * mem[b,n,m] (L2-hit re-read) ----
    float4 acc = make_float4(0.f, 0.f, 0.f, 0.f);
#pragma unroll 4
    for (int r = 0; r < 32; ++r) {
        int n = wid * 32 + r;
        float4 v = memb4[n * 32 + lane];
        float wn = s_w[n];
        acc.x += wn * v.x; acc.y += wn * v.y;
        acc.z += wn * v.z; acc.w += wn * v.w;
    }
    ((float4*)(s_part + wid * 128))[lane] = acc;
    __syncthreads();

    if (tid < 128) {
        float r = 0.f;
#pragma unroll
        for (int i = 0; i < 16; ++i) r += s_part[i * 128 + tid];
        d_out[b * 128 + tid] = r;            // output read_vec (first element)
    }
}

// ---------------------------------------------------------------------------
// Launch: fc projection, then fused head. Both plain launches (capturable).
// ---------------------------------------------------------------------------
extern "C" void kernel_launch(void* const* d_in, const int* in_sizes, int n_in,
                              void* d_out, int out_size) {
    const float* co     = (const float*)d_in[0];   // (512, 1024)
    const float* prevw  = (const float*)d_in[1];   // (512, 512)
    const float* mem    = (const float*)d_in[2];   // (512, 512, 128)
    const float* W      = (const float*)d_in[3];   // (1024, 134)
    const float* bias   = (const float*)d_in[4];   // (134,)

    fc_kernel<<<128, 256>>>(co, W, bias);
    ntm_kernel<<<512, 512>>>(mem, prevw, (float*)d_out);
}

// round 6
// speedup vs baseline: 1.5291x; 1.5291x over previous
#include <cuda_runtime.h>
#include <math.h>

#define EPSF 1e-8f
#define CR   416                         // rows cached in SMEM (of 512)
#define DYN_SMEM (CR * 128 * 4)          // 212992 B dynamic smem

// Scratch for FC output (512 x 134). __device__ global = allowed scratch.
__device__ float g_fc[512 * 134];

__device__ __forceinline__ float softplus_f(float x) {
    return (x > 20.0f) ? x : log1pf(expf(x));
}

// ---------------------------------------------------------------------------
// Kernel 1: out[b, j] = sum_c co[b, c] * W[c, j] + bias[j]
// Grid 128 CTAs x 4 batch rows. blockDim=(136,4): threadIdx.y splits C into
// 4 chunks of 256 -> 4x shorter dependency chains, 17 warps/CTA (was 4.2).
// Partials reduced in SMEM. Predict ~6 us (was ~90 us, latency-bound).
// ---------------------------------------------------------------------------
__global__ __launch_bounds__(544) void fc_kernel(const float* __restrict__ co,
                                                 const float* __restrict__ W,
                                                 const float* __restrict__ bias) {
    __shared__ __align__(16) float s_co[4 * 1024];   // 4 batch rows of co
    __shared__ float s_p[16 * 136];                  // partials [cz*4+row][j]
    const int b0 = blockIdx.x * 4;
    const int j  = threadIdx.x;                      // 0..135 (active < 134)
    const int cz = threadIdx.y;                      // 0..3 C-chunk
    const int tid = threadIdx.x + threadIdx.y * 136;

    const float4* co4 = (const float4*)(co + (size_t)b0 * 1024);
    float4* s4 = (float4*)s_co;
    for (int i = tid; i < 1024; i += 544) s4[i] = co4[i];
    __syncthreads();

    if (j < 134) {
        const float* wp = W + j;
        const int c0 = cz * 256;
        float a0 = 0.f, a1 = 0.f, a2 = 0.f, a3 = 0.f;
#pragma unroll 8
        for (int c = c0; c < c0 + 256; ++c) {
            float w = wp[c * 134];
            a0 += w * s_co[c];
            a1 += w * s_co[1024 + c];
            a2 += w * s_co[2048 + c];
            a3 += w * s_co[3072 + c];
        }
        s_p[(cz * 4 + 0) * 136 + j] = a0;
        s_p[(cz * 4 + 1) * 136 + j] = a1;
        s_p[(cz * 4 + 2) * 136 + j] = a2;
        s_p[(cz * 4 + 3) * 136 + j] = a3;
    }
    __syncthreads();

    if (cz == 0 && j < 134) {
        float bj = bias[j];
#pragma unroll
        for (int r = 0; r < 4; ++r) {
            float v = s_p[(0 + r) * 136 + j] + s_p[(4 + r) * 136 + j]
                    + s_p[(8 + r) * 136 + j] + s_p[(12 + r) * 136 + j] + bj;
            g_fc[(b0 + r) * 134 + j] = v;
        }
    }
}

// ---------------------------------------------------------------------------
// Block reduction helpers (512 threads = 16 warps).
// ---------------------------------------------------------------------------
__device__ __forceinline__ float block_sum(float v, float* s_red, int wid, int lane) {
#pragma unroll
    for (int o = 16; o; o >>= 1) v += __shfl_xor_sync(0xffffffffu, v, o);
    __syncthreads();
    if (lane == 0) s_red[wid] = v;
    __syncthreads();
    if (wid == 0) {
        float x = (lane < 16) ? s_red[lane] : 0.0f;
#pragma unroll
        for (int o = 8; o; o >>= 1) x += __shfl_xor_sync(0xffffffffu, x, o);
        if (lane == 0) s_red[16] = x;
    }
    __syncthreads();
    return s_red[16];
}

__device__ __forceinline__ float block_max(float v, float* s_red, int wid, int lane) {
#pragma unroll
    for (int o = 16; o; o >>= 1) v = fmaxf(v, __shfl_xor_sync(0xffffffffu, v, o));
    __syncthreads();
    if (lane == 0) s_red[wid] = v;
    __syncthreads();
    if (wid == 0) {
        float x = (lane < 16) ? s_red[lane] : -3.4e38f;
#pragma unroll
        for (int o = 8; o; o >>= 1) x = fmaxf(x, __shfl_xor_sync(0xffffffffu, x, o));
        if (lane == 0) s_red[16] = x;
    }
    __syncthreads();
    return s_red[16];
}

// ---------------------------------------------------------------------------
// Kernel 2: fused NTM head, 1 CTA per batch row, 512 threads, 1 CTA/SM.
// Phase B caches rows 0..415 in 208KB dynamic SMEM and rows 416..511 in
// registers (6 float4/thread) while computing cosine logits -> phase D does
// ZERO global re-read. DRAM traffic 245MB -> 134MB.
// Warp w owns rows n = w + 16k (k=0..31); cached iff k < 26.
// ---------------------------------------------------------------------------
__global__ __launch_bounds__(512, 1) void ntm_kernel(const float* __restrict__ mem,
                                                     const float* __restrict__ prev_w,
                                                     float* __restrict__ d_out) {
    extern __shared__ __align__(16) float s_cache[];     // CR*128 floats
    __shared__ __align__(16) float s_k[128];
    __shared__ float s_raw[8];
    __shared__ float s_scal[8];          // beta, g, s0,s1,s2, gamma, inv_norm_k
    __shared__ float s_w[512];
    __shared__ float s_red[32];
    // union region: [0,512)=logit, [512,1024)=wg, whole 2048 = warp partials
    __shared__ __align__(16) float s_u[2048];

    const int b    = blockIdx.x;
    const int tid  = threadIdx.x;
    const int wid  = tid >> 5;
    const int lane = tid & 31;

    // ---- Phase A: fc row -> k + scalar gates ----
    const float* fcb = g_fc + b * 134;
    if (tid < 128) s_k[tid] = fcb[tid];
    else if (tid < 134) s_raw[tid - 128] = fcb[tid];
    __syncthreads();

    if (tid == 0) {
        float beta = softplus_f(s_raw[0]);
        float g = 1.0f / (1.0f + expf(-s_raw[1]));
        float x0 = s_raw[2], x1 = s_raw[3], x2 = s_raw[4];
        float mx = fmaxf(x0, fmaxf(x1, x2));
        float e0 = expf(x0 - mx), e1 = expf(x1 - mx), e2 = expf(x2 - mx);
        float inv = 1.0f / (e0 + e1 + e2);
        s_scal[0] = beta; s_scal[1] = g;
        s_scal[2] = e0 * inv; s_scal[3] = e1 * inv; s_scal[4] = e2 * inv;
        s_scal[5] = 1.0f + softplus_f(s_raw[5]);
    }
    if (wid == 0) {
        float4 k4 = ((const float4*)s_k)[lane];
        float ss = k4.x * k4.x + k4.y * k4.y + k4.z * k4.z + k4.w * k4.w;
#pragma unroll
        for (int o = 16; o; o >>= 1) ss += __shfl_xor_sync(0xffffffffu, ss, o);
        if (lane == 0) s_scal[6] = 1.0f / (sqrtf(ss) + EPSF);
    }
    __syncthreads();

    const float beta   = s_scal[0];
    const float inv_nk = s_scal[6];
    const float4 k4 = ((const float4*)s_k)[lane];
    const float4* memb4 = (const float4*)(mem + (size_t)b * (512 * 128));
    float4* cache4 = (float4*)s_cache;
    float4 keep[6];                      // rows 416..511 live here (regs)

    // ---- Phase B: stream slab once; cache; cosine logits ----
    float4 va = memb4[(wid) * 32 + lane];
    float4 vb = memb4[(wid + 16) * 32 + lane];
#pragma unroll
    for (int k = 0; k < 32; k += 2) {
        const int n0 = wid + 16 * k;     // rows n0 and n0+16
        float4 v0 = va, v1 = vb;
        if (k + 2 < 32) {                // prefetch: overlap loads w/ shuffles
            va = memb4[(wid + 16 * (k + 2)) * 32 + lane];
            vb = memb4[(wid + 16 * (k + 3)) * 32 + lane];
        }
        if (k < 26) {
            cache4[n0 * 32 + lane] = v0;
            cache4[(n0 + 16) * 32 + lane] = v1;
        } else {
            keep[k - 26] = v0;
            keep[k - 25] = v1;
        }
        float d0 = v0.x * k4.x + v0.y * k4.y + v0.z * k4.z + v0.w * k4.w;
        float q0 = v0.x * v0.x + v0.y * v0.y + v0.z * v0.z + v0.w * v0.w;
        float d1 = v1.x * k4.x + v1.y * k4.y + v1.z * k4.z + v1.w * k4.w;
        float q1 = v1.x * v1.x + v1.y * v1.y + v1.z * v1.z + v1.w * v1.w;
#pragma unroll
        for (int o = 16; o; o >>= 1) {
            d0 += __shfl_xor_sync(0xffffffffu, d0, o);
            q0 += __shfl_xor_sync(0xffffffffu, q0, o);
            d1 += __shfl_xor_sync(0xffffffffu, d1, o);
            q1 += __shfl_xor_sync(0xffffffffu, q1, o);
        }
        if (lane == 0) {
            s_u[n0]      = beta * d0 * inv_nk / (sqrtf(q0) + EPSF);
            s_u[n0 + 16] = beta * d1 * inv_nk / (sqrtf(q1) + EPSF);
        }
    }
    __syncthreads();

    // ---- Phase C: softmax over N, gate, shift, sharpen ----
    float logit = s_u[tid];
    float vmax = block_max(logit, s_red, wid, lane);
    float e = expf(logit - vmax);
    float esum = block_sum(e, s_red, wid, lane);
    float w_c = e / esum;

    float g = s_scal[1];
    float wg = g * w_c + (1.0f - g) * prev_w[b * 512 + tid];
    s_u[512 + tid] = wg;
    __syncthreads();

    float ws = s_scal[2] * s_u[512 + ((tid + 511) & 511)]
             + s_scal[3] * wg
             + s_scal[4] * s_u[512 + ((tid + 1) & 511)];
    float wp = expf(s_scal[5] * logf(ws));           // ws > 0 always
    float psum = block_sum(wp, s_red, wid, lane);    // internal syncs order s_u reads
    float w = wp / (psum + EPSF);
    s_w[tid] = w;
    d_out[512 * 128 + b * 512 + tid] = w;            // output w
    __syncthreads();                                 // s_w ready; s_u free

    // ---- Phase D: read_vec from SMEM + regs only (no global re-read) ----
    float4 acc = make_float4(0.f, 0.f, 0.f, 0.f);
#pragma unroll
    for (int k = 0; k < 26; ++k) {
        const int n = wid + 16 * k;
        float4 v = cache4[n * 32 + lane];
        float wn = s_w[n];
        acc.x += wn * v.x; acc.y += wn * v.y;
        acc.z += wn * v.z; acc.w += wn * v.w;
    }
#pragma unroll
    for (int k = 26; k < 32; ++k) {
        const int n = wid + 16 * k;
        float4 v = keep[k - 26];
        float wn = s_w[n];
        acc.x += wn * v.x; acc.y += wn * v.y;
        acc.z += wn * v.z; acc.w += wn * v.w;
    }
    ((float4*)s_u)[wid * 32 + lane] = acc;           // 16 warps x 128 floats
    __syncthreads();

    if (tid < 128) {
        float r = 0.f;
#pragma unroll
        for (int i = 0; i < 16; ++i) r += s_u[i * 128 + tid];
        d_out[b * 128 + tid] = r;                    // output read_vec
    }
}

// ---------------------------------------------------------------------------
// Launch.
// ---------------------------------------------------------------------------
extern "C" void kernel_launch(void* const* d_in, const int* in_sizes, int n_in,
                              void* d_out, int out_size) {
    const float* co    = (const float*)d_in[0];   // (512, 1024)
    const float* prevw = (const float*)d_in[1];   // (512, 512)
    const float* mem   = (const float*)d_in[2];   // (512, 512, 128)
    const float* W     = (const float*)d_in[3];   // (1024, 134)
    const float* bias  = (const float*)d_in[4];   // (134,)

    cudaFuncSetAttribute(ntm_kernel, cudaFuncAttributeMaxDynamicSharedMemorySize,
                         DYN_SMEM);

    fc_kernel<<<128, dim3(136, 4)>>>(co, W, bias);
    ntm_kernel<<<512, 512, DYN_SMEM>>>(mem, prevw, (float*)d_out);
}

// round 8
// speedup vs baseline: 1.7126x; 1.1200x over previous
#include <cuda_runtime.h>
#include <math.h>

#define EPSF 1e-8f

// Scratch: 4 k-split partials of the FC output (4 x 512 x 134).
__device__ float g_fcp[4 * 512 * 134];

__device__ __forceinline__ float softplus_f(float x) {
    return (x > 20.0f) ? x : log1pf(expf(x));
}

// ---------------------------------------------------------------------------
// Kernel 1: FC partials. Grid (128 b-groups, 4 k-splits), block (136,4).
// Each CTA: 4 batch rows x K-chunk of 256 (cz splits into 64). Per-thread
// chain = 64 L2 loads (was 256) and 512 CTAs fill the chip.
// ---------------------------------------------------------------------------
__global__ __launch_bounds__(544) void fc_kernel(const float* __restrict__ co,
                                                 const float* __restrict__ W,
                                                 const float* __restrict__ bias) {
    __shared__ __align__(16) float s_co[4 * 256];    // 4 rows x 256 c-chunk
    __shared__ float s_p[16 * 136];                  // partials [cz*4+row][j]
    const int b0 = blockIdx.x * 4;
    const int ks = blockIdx.y;                       // k-split 0..3
    const int j  = threadIdx.x;                      // 0..135 (active < 134)
    const int cz = threadIdx.y;                      // 0..3
    const int tid = threadIdx.x + threadIdx.y * 136;

    // stage co[b0..b0+3][ks*256 .. ks*256+256) -> s_co
    for (int i = tid; i < 256; i += 544) {
        float4 x0 = *(const float4*)(co + (size_t)(b0 + 0) * 1024 + ks * 256 + i * 4);
        // i*4 indexes float4 elements: load as float4 over 256 floats => 64 f4/row
    }
    // simpler scalar-safe staging (256 floats/row, 1024 total):
    for (int i = tid; i < 1024; i += 544) {
        int r = i >> 8, c = i & 255;
        s_co[r * 256 + c] = co[(size_t)(b0 + r) * 1024 + ks * 256 + c];
    }
    __syncthreads();

    if (j < 134) {
        const float* wp = W + (size_t)(ks * 256) * 134 + j;
        const int c0 = cz * 64;
        float a0 = 0.f, a1 = 0.f, a2 = 0.f, a3 = 0.f;
#pragma unroll 16
        for (int c = c0; c < c0 + 64; ++c) {
            float w = wp[c * 134];
            a0 += w * s_co[c];
            a1 += w * s_co[256 + c];
            a2 += w * s_co[512 + c];
            a3 += w * s_co[768 + c];
        }
        s_p[(cz * 4 + 0) * 136 + j] = a0;
        s_p[(cz * 4 + 1) * 136 + j] = a1;
        s_p[(cz * 4 + 2) * 136 + j] = a2;
        s_p[(cz * 4 + 3) * 136 + j] = a3;
    }
    __syncthreads();

    if (cz == 0 && j < 134) {
        float bj = (ks == 0) ? bias[j] : 0.0f;
#pragma unroll
        for (int r = 0; r < 4; ++r) {
            float v = s_p[(0 + r) * 136 + j] + s_p[(4 + r) * 136 + j]
                    + s_p[(8 + r) * 136 + j] + s_p[(12 + r) * 136 + j] + bj;
            g_fcp[((size_t)ks * 512 + b0 + r) * 134 + j] = v;
        }
    }
}

// ---------------------------------------------------------------------------
// Block reduction helpers (512 threads = 16 warps).
// ---------------------------------------------------------------------------
__device__ __forceinline__ float block_sum(float v, float* s_red, int wid, int lane) {
#pragma unroll
    for (int o = 16; o; o >>= 1) v += __shfl_xor_sync(0xffffffffu, v, o);
    __syncthreads();
    if (lane == 0) s_red[wid] = v;
    __syncthreads();
    if (wid == 0) {
        float x = (lane < 16) ? s_red[lane] : 0.0f;
#pragma unroll
        for (int o = 8; o; o >>= 1) x += __shfl_xor_sync(0xffffffffu, x, o);
        if (lane == 0) s_red[16] = x;
    }
    __syncthreads();
    return s_red[16];
}

__device__ __forceinline__ float block_max(float v, float* s_red, int wid, int lane) {
#pragma unroll
    for (int o = 16; o; o >>= 1) v = fmaxf(v, __shfl_xor_sync(0xffffffffu, v, o));
    __syncthreads();
    if (lane == 0) s_red[wid] = v;
    __syncthreads();
    if (wid == 0) {
        float x = (lane < 16) ? s_red[lane] : -3.4e38f;
#pragma unroll
        for (int o = 8; o; o >>= 1) x = fmaxf(x, __shfl_xor_sync(0xffffffffu, x, o));
        if (lane == 0) s_red[16] = x;
    }
    __syncthreads();
    return s_red[16];
}

// ---------------------------------------------------------------------------
// Kernel 2: fused NTM head. 1 CTA per batch row, 512 threads, 2 CTAs/SM.
// The ENTIRE 256KB slab lives in registers: warp w owns rows n = w + 16k,
// thread holds float4 column `lane` of each of its 32 rows (128 regs).
// Phase B front-batches all 32 LDG.128 per thread (MLP~32/warp) -> DRAM-bound.
// Phase D consumes registers: no re-read, no SMEM cache.
// ---------------------------------------------------------------------------
__global__ __launch_bounds__(512, 2) void ntm_kernel(const float* __restrict__ mem,
                                                     const float* __restrict__ prev_w,
                                                     const float* __restrict__ bias_unused,
                                                     float* __restrict__ d_out) {
    __shared__ __align__(16) float s_k[128];
    __shared__ float s_raw[8];
    __shared__ float s_scal[8];      // beta, g, s0,s1,s2, gamma, inv_norm_k
    __shared__ float s_w[512];
    __shared__ float s_red[32];
    __shared__ __align__(16) float s_u[2048];   // logits / wg / warp partials

    const int b    = blockIdx.x;
    const int tid  = threadIdx.x;
    const int wid  = tid >> 5;
    const int lane = tid & 31;

    // ---- Phase A: sum FC partials -> k + scalar gates ----
    if (tid < 134) {
        const float* p = g_fcp + (size_t)b * 134 + tid;
        float v = p[0] + p[512 * 134] + p[2 * 512 * 134] + p[3 * 512 * 134];
        if (tid < 128) s_k[tid] = v;
        else           s_raw[tid - 128] = v;
    }
    __syncthreads();

    if (tid == 0) {
        float beta = softplus_f(s_raw[0]);
        float g = 1.0f / (1.0f + expf(-s_raw[1]));
        float x0 = s_raw[2], x1 = s_raw[3], x2 = s_raw[4];
        float mx = fmaxf(x0, fmaxf(x1, x2));
        float e0 = expf(x0 - mx), e1 = expf(x1 - mx), e2 = expf(x2 - mx);
        float inv = 1.0f / (e0 + e1 + e2);
        s_scal[0] = beta; s_scal[1] = g;
        s_scal[2] = e0 * inv; s_scal[3] = e1 * inv; s_scal[4] = e2 * inv;
        s_scal[5] = 1.0f + softplus_f(s_raw[5]);
    }
    if (wid == 0) {
        float4 k4 = ((const float4*)s_k)[lane];
        float ss = k4.x * k4.x + k4.y * k4.y + k4.z * k4.z + k4.w * k4.w;
#pragma unroll
        for (int o = 16; o; o >>= 1) ss += __shfl_xor_sync(0xffffffffu, ss, o);
        if (lane == 0) s_scal[6] = 1.0f / (sqrtf(ss) + EPSF);
    }
    __syncthreads();

    const float beta   = s_scal[0];
    const float inv_nk = s_scal[6];
    const float4 k4 = ((const float4*)s_k)[lane];
    const float4* memb4 = (const float4*)(mem + (size_t)b * (512 * 128));

    // ---- Phase B: front-batched load of the whole slab into registers ----
    float4 v[32];
#pragma unroll
    for (int k = 0; k < 32; ++k)
        v[k] = memb4[(wid + 16 * k) * 32 + lane];

    // cosine logits, two rows interleaved to overlap shuffle chains
#pragma unroll
    for (int k = 0; k < 32; k += 2) {
        const int n0 = wid + 16 * k;
        float4 v0 = v[k], v1 = v[k + 1];
        float d0 = v0.x * k4.x + v0.y * k4.y + v0.z * k4.z + v0.w * k4.w;
        float q0 = v0.x * v0.x + v0.y * v0.y + v0.z * v0.z + v0.w * v0.w;
        float d1 = v1.x * k4.x + v1.y * k4.y + v1.z * k4.z + v1.w * k4.w;
        float q1 = v1.x * v1.x + v1.y * v1.y + v1.z * v1.z + v1.w * v1.w;
#pragma unroll
        for (int o = 16; o; o >>= 1) {
            d0 += __shfl_xor_sync(0xffffffffu, d0, o);
            q0 += __shfl_xor_sync(0xffffffffu, q0, o);
            d1 += __shfl_xor_sync(0xffffffffu, d1, o);
            q1 += __shfl_xor_sync(0xffffffffu, q1, o);
        }
        if (lane == 0) {
            s_u[n0]      = beta * d0 * inv_nk / (sqrtf(q0) + EPSF);
            s_u[n0 + 16] = beta * d1 * inv_nk / (sqrtf(q1) + EPSF);
        }
    }
    __syncthreads();

    // ---- Phase C: softmax over N, gate, shift, sharpen ----
    float logit = s_u[tid];
    float vmax = block_max(logit, s_red, wid, lane);
    float e = expf(logit - vmax);
    float esum = block_sum(e, s_red, wid, lane);
    float w_c = e / esum;

    float g = s_scal[1];
    float wg = g * w_c + (1.0f - g) * prev_w[b * 512 + tid];
    s_u[512 + tid] = wg;
    __syncthreads();

    float ws = s_scal[2] * s_u[512 + ((tid + 511) & 511)]
             + s_scal[3] * wg
             + s_scal[4] * s_u[512 + ((tid + 1) & 511)];
    float wp = expf(s_scal[5] * logf(ws));          // ws > 0 (or 0 -> wp 0, matches ref)
    float psum = block_sum(wp, s_red, wid, lane);   // internal syncs order s_u reads
    float w = wp / (psum + EPSF);
    s_w[tid] = w;
    d_out[512 * 128 + b * 512 + tid] = w;           // output w (second element)
    __syncthreads();

    // ---- Phase D: read_vec purely from registers ----
    float4 acc = make_float4(0.f, 0.f, 0.f, 0.f);
#pragma unroll
    for (int k = 0; k < 32; ++k) {
        float wn = s_w[wid + 16 * k];               // broadcast LDS
        acc.x += wn * v[k].x; acc.y += wn * v[k].y;
        acc.z += wn * v[k].z; acc.w += wn * v[k].w;
    }
    ((float4*)s_u)[wid * 32 + lane] = acc;          // 16 warps x 128 floats
    __syncthreads();

    if (tid < 128) {
        float r = 0.f;
#pragma unroll
        for (int i = 0; i < 16; ++i) r += s_u[i * 128 + tid];
        d_out[b * 128 + tid] = r;                   // output read_vec (first element)
    }
}

// ---------------------------------------------------------------------------
// Launch.
// ---------------------------------------------------------------------------
extern "C" void kernel_launch(void* const* d_in, const int* in_sizes, int n_in,
                              void* d_out, int out_size) {
    const float* co    = (const float*)d_in[0];   // (512, 1024)
    const float* prevw = (const float*)d_in[1];   // (512, 512)
    const float* mem   = (const float*)d_in[2];   // (512, 512, 128)
    const float* W     = (const float*)d_in[3];   // (1024, 134)
    const float* bias  = (const float*)d_in[4];   // (134,)

    fc_kernel<<<dim3(128, 4), dim3(136, 4)>>>(co, W, bias);
    ntm_kernel<<<512, 512>>>(mem, prevw, bias, (float*)d_out);
}

// round 11
// speedup vs baseline: 2.1607x; 1.2617x over previous
#include <cuda_runtime.h>
#include <math.h>

#define EPSF 1e-8f
#define CR   416                          // rows cached in SMEM (of 512)
#define DYN_SMEM (CR * 128 * 4)           // 212992 B dynamic smem

// Scratch: 8 k-split partials of the FC output (8 x 512 x 134).
__device__ float g_fcp[8 * 512 * 134];

__device__ __forceinline__ float softplus_f(float x) {
    return (x > 20.0f) ? x : log1pf(expf(x));
}

// ---------------------------------------------------------------------------
// Kernel 1: FC partials. Grid (64 b-groups, 8 k-splits), block (136,4).
// 8 batch rows/CTA, K-chunk 128 (cz splits into 32). W slice per k-split is
// read by only 64 CTAs -> ~4.4MB L2 traffic (was ~275MB). FFMA floor ~2us.
// ---------------------------------------------------------------------------
__global__ __launch_bounds__(544) void fc_kernel(const float* __restrict__ co,
                                                 const float* __restrict__ W,
                                                 const float* __restrict__ bias) {
    __shared__ __align__(16) float s_co[8 * 128];    // 8 rows x 128 c-chunk
    __shared__ float s_p[4][8][136];                 // partials [cz][row][j]
    const int b0 = blockIdx.x * 8;
    const int ks = blockIdx.y;                       // k-split 0..7
    const int j  = threadIdx.x;                      // 0..135 (active < 134)
    const int cz = threadIdx.y;                      // 0..3
    const int tid = threadIdx.x + threadIdx.y * 136;

    // stage co[b0..b0+7][ks*128 .. ks*128+128) -> s_co
    for (int i = tid; i < 1024; i += 544) {
        int r = i >> 7, c = i & 127;
        s_co[r * 128 + c] = co[(size_t)(b0 + r) * 1024 + ks * 128 + c];
    }
    __syncthreads();

    if (j < 134) {
        const float* wp = W + (size_t)(ks * 128) * 134 + j;
        const int c0 = cz * 32;
        float a[8];
#pragma unroll
        for (int r = 0; r < 8; ++r) a[r] = 0.f;
#pragma unroll
        for (int c = c0; c < c0 + 32; ++c) {
            float w = wp[c * 134];
#pragma unroll
            for (int r = 0; r < 8; ++r) a[r] += w * s_co[r * 128 + c];
        }
#pragma unroll
        for (int r = 0; r < 8; ++r) s_p[cz][r][j] = a[r];
    }
    __syncthreads();

    if (cz == 0 && j < 134) {
        float bj = (ks == 0) ? bias[j] : 0.0f;
#pragma unroll
        for (int r = 0; r < 8; ++r) {
            float v = s_p[0][r][j] + s_p[1][r][j] + s_p[2][r][j] + s_p[3][r][j] + bj;
            g_fcp[((size_t)ks * 512 + b0 + r) * 134 + j] = v;
        }
    }
}

// ---------------------------------------------------------------------------
// Block reduction helpers (512 threads = 16 warps).
// ---------------------------------------------------------------------------
__device__ __forceinline__ float block_sum(float v, float* s_red, int wid, int lane) {
#pragma unroll
    for (int o = 16; o; o >>= 1) v += __shfl_xor_sync(0xffffffffu, v, o);
    __syncthreads();
    if (lane == 0) s_red[wid] = v;
    __syncthreads();
    if (wid == 0) {
        float x = (lane < 16) ? s_red[lane] : 0.0f;
#pragma unroll
        for (int o = 8; o; o >>= 1) x += __shfl_xor_sync(0xffffffffu, x, o);
        if (lane == 0) s_red[16] = x;
    }
    __syncthreads();
    return s_red[16];
}

__device__ __forceinline__ float block_max(float v, float* s_red, int wid, int lane) {
#pragma unroll
    for (int o = 16; o; o >>= 1) v = fmaxf(v, __shfl_xor_sync(0xffffffffu, v, o));
    __syncthreads();
    if (lane == 0) s_red[wid] = v;
    __syncthreads();
    if (wid == 0) {
        float x = (lane < 16) ? s_red[lane] : -3.4e38f;
#pragma unroll
        for (int o = 8; o; o >>= 1) x = fmaxf(x, __shfl_xor_sync(0xffffffffu, x, o));
        if (lane == 0) s_red[16] = x;
    }
    __syncthreads();
    return s_red[16];
}

// ---------------------------------------------------------------------------
// Kernel 2: fused NTM head. 1 CTA/row, 512 threads, 1 CTA/SM (128-reg budget,
// NO spill). Slab storage: rows 0..415 in 208KB SMEM, rows 416..511 in regs
// (keep[6]). Phase B double-buffers groups of 4 front-batched LDG.128
// (32KB/SM in flight > ~16KB needed) so DRAM stays saturated while the
// shfl reduction chains retire. Phase D touches no global memory.
// Warp w owns rows n = w + 16k (k=0..31); cached iff k < 26.
// ---------------------------------------------------------------------------
__global__ __launch_bounds__(512, 1) void ntm_kernel(const float* __restrict__ mem,
                                                     const float* __restrict__ prev_w,
                                                     float* __restrict__ d_out) {
    extern __shared__ __align__(16) float s_cache[];     // CR*128 floats
    __shared__ __align__(16) float s_k[128];
    __shared__ float s_raw[8];
    __shared__ float s_scal[8];          // beta, g, s0,s1,s2, gamma, inv_norm_k
    __shared__ float s_w[512];
    __shared__ float s_red[32];
    __shared__ __align__(16) float s_u[2048];   // logits / wg / warp partials

    const int b    = blockIdx.x;
    const int tid  = threadIdx.x;
    const int wid  = tid >> 5;
    const int lane = tid & 31;

    // ---- Phase A: sum 8 FC partials -> k + scalar gates ----
    if (tid < 134) {
        const float* p = g_fcp + (size_t)b * 134 + tid;
        float v = 0.f;
#pragma unroll
        for (int ks = 0; ks < 8; ++ks) v += p[(size_t)ks * 512 * 134];
        if (tid < 128) s_k[tid] = v;
        else           s_raw[tid - 128] = v;
    }
    __syncthreads();

    if (tid == 0) {
        float beta = softplus_f(s_raw[0]);
        float g = 1.0f / (1.0f + expf(-s_raw[1]));
        float x0 = s_raw[2], x1 = s_raw[3], x2 = s_raw[4];
        float mx = fmaxf(x0, fmaxf(x1, x2));
        float e0 = expf(x0 - mx), e1 = expf(x1 - mx), e2 = expf(x2 - mx);
        float inv = 1.0f / (e0 + e1 + e2);
        s_scal[0] = beta; s_scal[1] = g;
        s_scal[2] = e0 * inv; s_scal[3] = e1 * inv; s_scal[4] = e2 * inv;
        s_scal[5] = 1.0f + softplus_f(s_raw[5]);
    }
    if (wid == 0) {
        float4 k4 = ((const float4*)s_k)[lane];
        float ss = k4.x * k4.x + k4.y * k4.y + k4.z * k4.z + k4.w * k4.w;
#pragma unroll
        for (int o = 16; o; o >>= 1) ss += __shfl_xor_sync(0xffffffffu, ss, o);
        if (lane == 0) s_scal[6] = 1.0f / (sqrtf(ss) + EPSF);
    }
    __syncthreads();

    const float beta   = s_scal[0];
    const float inv_nk = s_scal[6];
    const float4 k4 = ((const float4*)s_k)[lane];
    const float4* memb4 = (const float4*)(mem + (size_t)b * (512 * 128));
    float4* cache4 = (float4*)s_cache;
    float4 keep[6];                      // rows with k = 26..31 (regs)
    float4 buf[2][4];                    // double-buffered load groups

    // ---- Phase B: stream slab once (groups of 4, double-buffered) ----
#pragma unroll
    for (int i = 0; i < 4; ++i)
        buf[0][i] = memb4[(wid + 16 * i) * 32 + lane];

#pragma unroll
    for (int g = 0; g < 8; ++g) {
        const int cur = g & 1, nxt = cur ^ 1;
        if (g < 7) {
#pragma unroll
            for (int i = 0; i < 4; ++i)
                buf[nxt][i] = memb4[(wid + 16 * (4 * (g + 1) + i)) * 32 + lane];
        }
        // stash rows
#pragma unroll
        for (int i = 0; i < 4; ++i) {
            const int k = 4 * g + i;
            const int n = wid + 16 * k;
            if (k < 26) cache4[n * 32 + lane] = buf[cur][i];
            else        keep[k - 26] = buf[cur][i];
        }
        // cosine logits: 4 rows x 2 values interleaved (8 shfl streams)
        float d[4], q[4];
#pragma unroll
        for (int i = 0; i < 4; ++i) {
            float4 v = buf[cur][i];
            d[i] = v.x * k4.x + v.y * k4.y + v.z * k4.z + v.w * k4.w;
            q[i] = v.x * v.x + v.y * v.y + v.z * v.z + v.w * v.w;
        }
#pragma unroll
        for (int o = 16; o; o >>= 1) {
#pragma unroll
            for (int i = 0; i < 4; ++i) {
                d[i] += __shfl_xor_sync(0xffffffffu, d[i], o);
                q[i] += __shfl_xor_sync(0xffffffffu, q[i], o);
            }
        }
        if (lane == 0) {
#pragma unroll
            for (int i = 0; i < 4; ++i) {
                const int n = wid + 16 * (4 * g + i);
                s_u[n] = beta * d[i] * inv_nk / (sqrtf(q[i]) + EPSF);
            }
        }
    }
    __syncthreads();

    // ---- Phase C: softmax over N, gate, shift, sharpen ----
    float logit = s_u[tid];
    float vmax = block_max(logit, s_red, wid, lane);
    float e = expf(logit - vmax);
    float esum = block_sum(e, s_red, wid, lane);
    float w_c = e / esum;

    float g = s_scal[1];
    float wg = g * w_c + (1.0f - g) * prev_w[b * 512 + tid];
    s_u[512 + tid] = wg;
    __syncthreads();

    float ws = s_scal[2] * s_u[512 + ((tid + 511) & 511)]
             + s_scal[3] * wg
             + s_scal[4] * s_u[512 + ((tid + 1) & 511)];
    float wp = expf(s_scal[5] * logf(ws));          // ws > 0 always
    float psum = block_sum(wp, s_red, wid, lane);   // internal syncs order s_u reads
    float w = wp / (psum + EPSF);
    s_w[tid] = w;
    d_out[512 * 128 + b * 512 + tid] = w;           // output w (second element)
    __syncthreads();                                // s_w ready; s_u free

    // ---- Phase D: read_vec from SMEM cache + keep regs only ----
    float4 acc = make_float4(0.f, 0.f, 0.f, 0.f);
#pragma unroll
    for (int k = 0; k < 26; ++k) {
        const int n = wid + 16 * k;
        float4 v = cache4[n * 32 + lane];
        float wn = s_w[n];
        acc.x += wn * v.x; acc.y += wn * v.y;
        acc.z += wn * v.z; acc.w += wn * v.w;
    }
#pragma unroll
    for (int k = 26; k < 32; ++k) {
        float wn = s_w[wid + 16 * k];
        acc.x += wn * keep[k - 26].x; acc.y += wn * keep[k - 26].y;
        acc.z += wn * keep[k - 26].z; acc.w += wn * keep[k - 26].w;
    }
    ((float4*)s_u)[wid * 32 + lane] = acc;          // 16 warps x 128 floats
    __syncthreads();

    if (tid < 128) {
        float r = 0.f;
#pragma unroll
        for (int i = 0; i < 16; ++i) r += s_u[i * 128 + tid];
        d_out[b * 128 + tid] = r;                   // output read_vec
    }
}

// ---------------------------------------------------------------------------
// Launch.
// ---------------------------------------------------------------------------
extern "C" void kernel_launch(void* const* d_in, const int* in_sizes, int n_in,
                              void* d_out, int out_size) {
    const float* co    = (const float*)d_in[0];   // (512, 1024)
    const float* prevw = (const float*)d_in[1];   // (512, 512)
    const float* mem   = (const float*)d_in[2];   // (512, 512, 128)
    const float* W     = (const float*)d_in[3];   // (1024, 134)
    const float* bias  = (const float*)d_in[4];   // (134,)

    cudaFuncSetAttribute(ntm_kernel, cudaFuncAttributeMaxDynamicSharedMemorySize,
                         DYN_SMEM);

    fc_kernel<<<dim3(64, 8), dim3(136, 4)>>>(co, W, bias);
    ntm_kernel<<<512, 512, DYN_SMEM>>>(mem, prevw, (float*)d_out);
}